// round 11
// baseline (speedup 1.0000x reference)
#include <cuda_runtime.h>
#include <cuda_bf16.h>
#include <stdint.h>

#define N_NODES 100000
#define NE      1600000
#define IN_DIM  256
#define HID     128
#define SCAN_B  ((N_NODES + 1023) / 1024)   // 98 scan blocks

// ---------------- scratch (static device globals; no allocation) ------------
__device__ int   d_src32[NE];
__device__ int   d_dst32[NE];
__device__ int   d_srcs[NE];       // CSR-permuted source indices (by dst)
__device__ int   d_cnt[N_NODES];
__device__ int   d_rowptr[N_NODES];
__device__ int   d_cursor[N_NODES];
__device__ float d_dinv[N_NODES];
__device__ int   d_bsum[SCAN_B];
__device__ int   d_boff[SCAN_B];
__device__ float d_h[(size_t)N_NODES * HID];
__device__ float d_t[(size_t)N_NODES * HID];
__device__ float d_w2h[HID * 2];   // folded W2 @ Wh  [128,2]
__device__ float d_bh2[2];         // folded b2 @ Wh + bh
__device__ int   g_is64;

// ---------------- helpers -----------------------------------------------------
__device__ __forceinline__ unsigned pack_bf16x2(float k_even, float k_odd) {
    unsigned r;
    asm("cvt.rn.bf16x2.f32 %0, %1, %2;" : "=r"(r) : "f"(k_odd), "f"(k_even));
    return r;
}
__device__ __forceinline__ void mma_bf16(float* c, unsigned a0, unsigned a1,
                                         unsigned a2, unsigned a3,
                                         unsigned b0, unsigned b1) {
    asm("mma.sync.aligned.m16n8k16.row.col.f32.bf16.bf16.f32 "
        "{%0,%1,%2,%3}, {%4,%5,%6,%7}, {%8,%9}, {%0,%1,%2,%3};"
        : "+f"(c[0]), "+f"(c[1]), "+f"(c[2]), "+f"(c[3])
        : "r"(a0), "r"(a1), "r"(a2), "r"(a3), "r"(b0), "r"(b1));
}

// ---------------- edge dtype detection + conversion + count ------------------
__global__ void k_detect(const int* __restrict__ w) {
    int ok = 1;
    for (int i = 0; i < 64; i++) {
        if (w[2 * i + 1] != 0) { ok = 0; break; }
    }
    g_is64 = ok;
}

__global__ void k_zero_cnt() {
    int i = blockIdx.x * blockDim.x + threadIdx.x;
    if (i < N_NODES) d_cnt[i] = 0;
}

__global__ void k_convert_count(const void* __restrict__ ei) {
    int e = blockIdx.x * blockDim.x + threadIdx.x;
    if (e >= NE) return;
    int s, d;
    if (g_is64) {
        const long long* p = (const long long*)ei;
        s = (int)p[e];
        d = (int)p[e + NE];
    } else {
        const int* p = (const int*)ei;
        s = p[e];
        d = p[e + NE];
    }
    d_src32[e] = s;
    d_dst32[e] = d;
    atomicAdd(&d_cnt[d], 1);
}

// ---------------- parallel 3-phase scan --------------------------------------
__global__ void __launch_bounds__(1024) k_scan1() {
    __shared__ int wsum[32];
    const int tid  = threadIdx.x;
    const int lane = tid & 31;
    const int w    = tid >> 5;
    const int gid  = blockIdx.x * 1024 + tid;

    int c = (gid < N_NODES) ? d_cnt[gid] : 0;
    int v = c;
#pragma unroll
    for (int o = 1; o < 32; o <<= 1) {
        int t = __shfl_up_sync(0xFFFFFFFFu, v, o);
        if (lane >= o) v += t;
    }
    if (lane == 31) wsum[w] = v;
    __syncthreads();
    if (w == 0) {
        int s = wsum[lane];
#pragma unroll
        for (int o = 1; o < 32; o <<= 1) {
            int t = __shfl_up_sync(0xFFFFFFFFu, s, o);
            if (lane >= o) s += t;
        }
        wsum[lane] = s;
    }
    __syncthreads();
    int excl = v - c + (w ? wsum[w - 1] : 0);
    if (gid < N_NODES) d_rowptr[gid] = excl;
    if (tid == 1023) d_bsum[blockIdx.x] = wsum[31];
}

__global__ void k_scan2() {
    __shared__ int s[128];
    const int t = threadIdx.x;
    s[t] = (t < SCAN_B) ? d_bsum[t] : 0;
    __syncthreads();
    for (int o = 1; o < 128; o <<= 1) {
        int v = (t >= o) ? s[t - o] : 0;
        __syncthreads();
        s[t] += v;
        __syncthreads();
    }
    if (t < SCAN_B) d_boff[t] = (t ? s[t - 1] : 0);
}

__global__ void k_scan3() {
    const int gid = blockIdx.x * blockDim.x + threadIdx.x;
    if (gid >= N_NODES) return;
    int rp = d_rowptr[gid] + d_boff[gid >> 10];
    d_rowptr[gid] = rp;
    d_cursor[gid] = rp;
    d_dinv[gid] = rsqrtf((float)(d_cnt[gid] + 1));  // +1 = self loop
}

__global__ void k_fill() {
    int e = blockIdx.x * blockDim.x + threadIdx.x;
    if (e >= NE) return;
    int dd = d_dst32[e];
    int pos = atomicAdd(&d_cursor[dd], 1);
    d_srcs[pos] = d_src32[e];
}

// ---------------- weight folding: W2h = W2 @ Wh, bh2 = b2 @ Wh + bh ---------
__global__ void k_fold(const float* __restrict__ W2,
                       const float* __restrict__ Wh,
                       const float* __restrict__ b2,
                       const float* __restrict__ bh) {
    const int i = threadIdx.x;           // 256 threads
    const int k = i >> 1, j = i & 1;
    float s = 0.f;
#pragma unroll 8
    for (int m = 0; m < HID; m++)
        s += W2[(size_t)k * HID + m] * Wh[m * 2 + j];
    d_w2h[k * 2 + j] = s;
    if (k == 0) {
        float t = bh[j];
        for (int m = 0; m < HID; m++) t += b2[m] * Wh[m * 2 + j];
        d_bh2[j] = t;
    }
}

// ---------------- tensor-core GEMM ------------------------------------------
// C[M,128] = act(A[M,K] @ W[K,128] + b), split-bf16 3-term compensation.
// 8 warps = 4 m-groups x 2 n-halves; warp tile 32 rows x 64 cols
// (2 m16 tiles x 8 n8 blocks) -> W fragment loads amortized over 2 m-tiles.
#define PAD 20
template <int K, bool RELU, bool BIAS>
__global__ void __launch_bounds__(256) k_gemm_tc(const float* __restrict__ A,
                                                 const float* __restrict__ W,
                                                 const float* __restrict__ bias,
                                                 float* __restrict__ C, int M) {
    __shared__ unsigned sAhi[128][PAD];
    __shared__ unsigned sAlo[128][PAD];
    __shared__ unsigned sWhi[128][PAD];
    __shared__ unsigned sWlo[128][PAD];

    const int tid  = threadIdx.x;
    const int warp = tid >> 5;
    const int lane = tid & 31;
    const int g    = lane >> 2;
    const int tig  = lane & 3;
    const int mw   = (warp >> 1) * 32;    // warp's m-group (0,32,64,96)
    const int nw   = (warp & 1) * 64;     // warp's n-half (0,64)
    const int row0 = blockIdx.x * 128;

    float acc[2][8][4];
#pragma unroll
    for (int mt = 0; mt < 2; mt++)
#pragma unroll
        for (int nb = 0; nb < 8; nb++)
#pragma unroll
            for (int i = 0; i < 4; i++) acc[mt][nb][i] = 0.f;

    for (int kc = 0; kc < K; kc += 32) {
        // ---- A tile: 128 rows x 32 k = 1024 float4 --------------------------
#pragma unroll
        for (int i = 0; i < 4; i++) {
            int idx = tid + i * 256;
            int r = idx >> 3, c4 = idx & 7;
            int grow = row0 + r;
            float4 v = make_float4(0.f, 0.f, 0.f, 0.f);
            if (grow < M)
                v = *(const float4*)(A + (size_t)grow * K + kc + c4 * 4);
            float hx = __bfloat162float(__float2bfloat16(v.x));
            float hy = __bfloat162float(__float2bfloat16(v.y));
            float hz = __bfloat162float(__float2bfloat16(v.z));
            float hw = __bfloat162float(__float2bfloat16(v.w));
            sAhi[r][c4 * 2 + 0] = pack_bf16x2(hx, hy);
            sAhi[r][c4 * 2 + 1] = pack_bf16x2(hz, hw);
            sAlo[r][c4 * 2 + 0] = pack_bf16x2(v.x - hx, v.y - hy);
            sAlo[r][c4 * 2 + 1] = pack_bf16x2(v.z - hz, v.w - hw);
        }
        // ---- W tile (transposed) --------------------------------------------
#pragma unroll
        for (int i = 0; i < 8; i++) {
            int idx = tid + i * 256;
            int n = idx & 127, kp = idx >> 7;
            float w0 = W[(size_t)(kc + 2 * kp)     * 128 + n];
            float w1 = W[(size_t)(kc + 2 * kp + 1) * 128 + n];
            float h0 = __bfloat162float(__float2bfloat16(w0));
            float h1 = __bfloat162float(__float2bfloat16(w1));
            sWhi[n][kp] = pack_bf16x2(h0, h1);
            sWlo[n][kp] = pack_bf16x2(w0 - h0, w1 - h1);
        }
        __syncthreads();

#pragma unroll
        for (int kk = 0; kk < 2; kk++) {
            const int kp = kk * 8 + tig;
            unsigned ah[2][4], al[2][4];
#pragma unroll
            for (int mt = 0; mt < 2; mt++) {
                const int mb = mw + mt * 16;
                ah[mt][0] = sAhi[mb + g][kp];
                ah[mt][1] = sAhi[mb + g + 8][kp];
                ah[mt][2] = sAhi[mb + g][kp + 4];
                ah[mt][3] = sAhi[mb + g + 8][kp + 4];
                al[mt][0] = sAlo[mb + g][kp];
                al[mt][1] = sAlo[mb + g + 8][kp];
                al[mt][2] = sAlo[mb + g][kp + 4];
                al[mt][3] = sAlo[mb + g + 8][kp + 4];
            }
#pragma unroll
            for (int nb = 0; nb < 8; nb++) {
                const int nr = nw + nb * 8 + g;
                unsigned bh0 = sWhi[nr][kp];
                unsigned bh1 = sWhi[nr][kp + 4];
                unsigned bl0 = sWlo[nr][kp];
                unsigned bl1 = sWlo[nr][kp + 4];
#pragma unroll
                for (int mt = 0; mt < 2; mt++) {
                    mma_bf16(acc[mt][nb], ah[mt][0], ah[mt][1], ah[mt][2], ah[mt][3], bh0, bh1);
                    mma_bf16(acc[mt][nb], ah[mt][0], ah[mt][1], ah[mt][2], ah[mt][3], bl0, bl1);
                    mma_bf16(acc[mt][nb], al[mt][0], al[mt][1], al[mt][2], al[mt][3], bh0, bh1);
                }
            }
        }
        __syncthreads();
    }

    // ---- epilogue -----------------------------------------------------------
#pragma unroll
    for (int mt = 0; mt < 2; mt++) {
        const int r0 = row0 + mw + mt * 16 + g;
        const int r1 = r0 + 8;
#pragma unroll
        for (int nb = 0; nb < 8; nb++) {
            int col = nw + nb * 8 + tig * 2;
            float b0 = 0.f, b1 = 0.f;
            if (BIAS) { b0 = bias[col]; b1 = bias[col + 1]; }
            float2 v0, v1;
            v0.x = acc[mt][nb][0] + b0; v0.y = acc[mt][nb][1] + b1;
            v1.x = acc[mt][nb][2] + b0; v1.y = acc[mt][nb][3] + b1;
            if (RELU) {
                v0.x = fmaxf(v0.x, 0.f); v0.y = fmaxf(v0.y, 0.f);
                v1.x = fmaxf(v1.x, 0.f); v1.y = fmaxf(v1.y, 0.f);
            }
            if (r0 < M) *(float2*)(C + (size_t)r0 * 128 + col) = v0;
            if (r1 < M) *(float2*)(C + (size_t)r1 * 128 + col) = v1;
        }
    }
}

// ---------------- GCN aggregate (layer 1): warp per destination node --------
__global__ void __launch_bounds__(256) k_aggregate(const float* __restrict__ t,
                                                   const float* __restrict__ b,
                                                   float* __restrict__ hout) {
    const int wid  = (blockIdx.x * blockDim.x + threadIdx.x) >> 5;
    const int lane = threadIdx.x & 31;
    if (wid >= N_NODES) return;
    const int d = wid;

    const float4* t4 = (const float4*)t;
    const float dd = d_dinv[d];

    float4 a0 = t4[d * 32 + lane];   // self term
    a0.x *= dd; a0.y *= dd; a0.z *= dd; a0.w *= dd;
    float4 a1 = make_float4(0.f, 0.f, 0.f, 0.f);

    const int beg = d_rowptr[d];
    const int num = d_cnt[d];
    int j = 0;
    for (; j + 2 <= num; j += 2) {
        int s0 = d_srcs[beg + j];
        int s1 = d_srcs[beg + j + 1];
        float ds0 = d_dinv[s0];
        float ds1 = d_dinv[s1];
        float4 v0 = t4[s0 * 32 + lane];
        float4 v1 = t4[s1 * 32 + lane];
        a0.x += v0.x * ds0; a0.y += v0.y * ds0;
        a0.z += v0.z * ds0; a0.w += v0.w * ds0;
        a1.x += v1.x * ds1; a1.y += v1.y * ds1;
        a1.z += v1.z * ds1; a1.w += v1.w * ds1;
    }
    if (j < num) {
        int s = d_srcs[beg + j];
        float ds = d_dinv[s];
        float4 v = t4[s * 32 + lane];
        a0.x += v.x * ds; a0.y += v.y * ds;
        a0.z += v.z * ds; a0.w += v.w * ds;
    }

    float4 bv = ((const float4*)b)[lane];
    float4 o;
    o.x = (a0.x + a1.x) * dd + bv.x;
    o.y = (a0.y + a1.y) * dd + bv.y;
    o.z = (a0.z + a1.z) * dd + bv.z;
    o.w = (a0.w + a1.w) * dd + bv.w;
    ((float4*)hout)[(size_t)d * 32 + lane] = o;
}

// ---------------- fused aggregate + head ------------------------------------
// out[d] = (P·h1)[d] @ W2h + bh2   (layer-2 GEMM folded into the 128x2 head)
__global__ void __launch_bounds__(256) k_agg_head(const float* __restrict__ h1,
                                                  float* __restrict__ out) {
    const int wid  = (blockIdx.x * blockDim.x + threadIdx.x) >> 5;
    const int lane = threadIdx.x & 31;
    if (wid >= N_NODES) return;
    const int d = wid;

    const float4* t4 = (const float4*)h1;
    const float dd = d_dinv[d];

    float4 a0 = t4[d * 32 + lane];   // self term
    a0.x *= dd; a0.y *= dd; a0.z *= dd; a0.w *= dd;
    float4 a1 = make_float4(0.f, 0.f, 0.f, 0.f);

    const int beg = d_rowptr[d];
    const int num = d_cnt[d];
    int j = 0;
    for (; j + 2 <= num; j += 2) {
        int s0 = d_srcs[beg + j];
        int s1 = d_srcs[beg + j + 1];
        float ds0 = d_dinv[s0];
        float ds1 = d_dinv[s1];
        float4 v0 = t4[s0 * 32 + lane];
        float4 v1 = t4[s1 * 32 + lane];
        a0.x += v0.x * ds0; a0.y += v0.y * ds0;
        a0.z += v0.z * ds0; a0.w += v0.w * ds0;
        a1.x += v1.x * ds1; a1.y += v1.y * ds1;
        a1.z += v1.z * ds1; a1.w += v1.w * ds1;
    }
    if (j < num) {
        int s = d_srcs[beg + j];
        float ds = d_dinv[s];
        float4 v = t4[s * 32 + lane];
        a0.x += v.x * ds; a0.y += v.y * ds;
        a0.z += v.z * ds; a0.w += v.w * ds;
    }

    float4 a;
    a.x = (a0.x + a1.x) * dd;
    a.y = (a0.y + a1.y) * dd;
    a.z = (a0.z + a1.z) * dd;
    a.w = (a0.w + a1.w) * dd;

    float4 w0 = *(const float4*)(d_w2h + lane * 8);
    float4 w1 = *(const float4*)(d_w2h + lane * 8 + 4);
    float p0 = a.x * w0.x + a.y * w0.z + a.z * w1.x + a.w * w1.z;
    float p1 = a.x * w0.y + a.y * w0.w + a.z * w1.y + a.w * w1.w;
#pragma unroll
    for (int off = 16; off; off >>= 1) {
        p0 += __shfl_xor_sync(0xFFFFFFFFu, p0, off);
        p1 += __shfl_xor_sync(0xFFFFFFFFu, p1, off);
    }
    if (lane == 0) {
        out[d * 2 + 0] = p0 + d_bh2[0];
        out[d * 2 + 1] = p1 + d_bh2[1];
    }
}

// ---------------- launch -----------------------------------------------------
extern "C" void kernel_launch(void* const* d_in, const int* in_sizes, int n_in,
                              void* d_out, int out_size) {
    const void*  ei = d_in[0];
    const float* x  = (const float*)d_in[1];
    const float* Wi = (const float*)d_in[2];
    const float* bi = (const float*)d_in[3];
    const float* W1 = (const float*)d_in[4];
    const float* b1 = (const float*)d_in[5];
    const float* W2 = (const float*)d_in[6];
    const float* b2 = (const float*)d_in[7];
    const float* Wh = (const float*)d_in[8];
    const float* bh = (const float*)d_in[9];
    float* out = (float*)d_out;

    float *h, *t;
    cudaGetSymbolAddress((void**)&h, d_h);
    cudaGetSymbolAddress((void**)&t, d_t);

    const int EB = (NE + 255) / 256;
    const int NB = (N_NODES + 255) / 256;
    const int GB = (N_NODES + 127) / 128;
    const int WB = (N_NODES + 7) / 8;

    // Launch order keeps the big GEMM at index 3 (ncu's capture slot).
    k_detect<<<1, 1>>>((const int*)ei);                                // 0
    k_zero_cnt<<<NB, 256>>>();                                         // 1
    k_convert_count<<<EB, 256>>>(ei);                                  // 2
    k_gemm_tc<IN_DIM, true, true><<<GB, 256>>>(x, Wi, bi, h, N_NODES); // 3 <- profiled
    k_scan1<<<SCAN_B, 1024>>>();                                       // 4
    k_scan2<<<1, 128>>>();                                             // 5
    k_scan3<<<NB, 256>>>();                                            // 6
    k_fill<<<EB, 256>>>();                                             // 7
    k_fold<<<1, 256>>>(W2, Wh, b2, bh);                                // 8

    // layer 1: t = h @ W1 ; h = P·t + b1
    k_gemm_tc<HID, false, false><<<GB, 256>>>(h, W1, nullptr, t, N_NODES);
    k_aggregate<<<WB, 256>>>(t, b1, h);

    // layer 2 + head fused: out = (P·h) @ (W2@Wh) + (b2@Wh + bh)
    k_agg_head<<<WB, 256>>>(h, out);
}

// round 13
// speedup vs baseline: 1.0021x; 1.0021x over previous
#include <cuda_runtime.h>
#include <cuda_bf16.h>
#include <stdint.h>

#define N_NODES 100000
#define NE      1600000
#define IN_DIM  256
#define HID     128
#define SCAN_B  ((N_NODES + 1023) / 1024)   // 98 scan blocks

// ---------------- scratch (static device globals; no allocation) ------------
__device__ int   d_src32[NE];
__device__ int   d_dst32[NE];
__device__ int   d_srcs[NE];       // CSR-permuted source indices (by dst)
__device__ int   d_cnt[N_NODES];
__device__ int   d_rowptr[N_NODES];
__device__ int   d_cursor[N_NODES];
__device__ float d_dinv[N_NODES];
__device__ int   d_bsum[SCAN_B];
__device__ int   d_boff[SCAN_B];
__device__ float d_h[(size_t)N_NODES * HID];
__device__ float d_t[(size_t)N_NODES * HID];
__device__ float d_w2h[HID * 2];   // folded W2 @ Wh  [128,2]
__device__ float d_bh2[2];         // folded b2 @ Wh + bh
__device__ int   g_is64;

// ---------------- helpers -----------------------------------------------------
__device__ __forceinline__ unsigned pack_bf16x2(float k_even, float k_odd) {
    unsigned r;
    asm("cvt.rn.bf16x2.f32 %0, %1, %2;" : "=r"(r) : "f"(k_odd), "f"(k_even));
    return r;
}
__device__ __forceinline__ void mma_bf16(float* c, unsigned a0, unsigned a1,
                                         unsigned a2, unsigned a3,
                                         unsigned b0, unsigned b1) {
    asm("mma.sync.aligned.m16n8k16.row.col.f32.bf16.bf16.f32 "
        "{%0,%1,%2,%3}, {%4,%5,%6,%7}, {%8,%9}, {%0,%1,%2,%3};"
        : "+f"(c[0]), "+f"(c[1]), "+f"(c[2]), "+f"(c[3])
        : "r"(a0), "r"(a1), "r"(a2), "r"(a3), "r"(b0), "r"(b1));
}

// ---------------- edge dtype detection + conversion + count ------------------
__global__ void k_detect(const int* __restrict__ w) {
    int ok = 1;
    for (int i = 0; i < 64; i++) {
        if (w[2 * i + 1] != 0) { ok = 0; break; }
    }
    g_is64 = ok;
}

__global__ void k_zero_cnt() {
    int i = blockIdx.x * blockDim.x + threadIdx.x;
    if (i < N_NODES) d_cnt[i] = 0;
}

__global__ void k_convert_count(const void* __restrict__ ei) {
    int e = blockIdx.x * blockDim.x + threadIdx.x;
    if (e >= NE) return;
    int s, d;
    if (g_is64) {
        const long long* p = (const long long*)ei;
        s = (int)p[e];
        d = (int)p[e + NE];
    } else {
        const int* p = (const int*)ei;
        s = p[e];
        d = p[e + NE];
    }
    d_src32[e] = s;
    d_dst32[e] = d;
    atomicAdd(&d_cnt[d], 1);
}

// ---------------- parallel 3-phase scan --------------------------------------
__global__ void __launch_bounds__(1024) k_scan1() {
    __shared__ int wsum[32];
    const int tid  = threadIdx.x;
    const int lane = tid & 31;
    const int w    = tid >> 5;
    const int gid  = blockIdx.x * 1024 + tid;

    int c = (gid < N_NODES) ? d_cnt[gid] : 0;
    int v = c;
#pragma unroll
    for (int o = 1; o < 32; o <<= 1) {
        int t = __shfl_up_sync(0xFFFFFFFFu, v, o);
        if (lane >= o) v += t;
    }
    if (lane == 31) wsum[w] = v;
    __syncthreads();
    if (w == 0) {
        int s = wsum[lane];
#pragma unroll
        for (int o = 1; o < 32; o <<= 1) {
            int t = __shfl_up_sync(0xFFFFFFFFu, s, o);
            if (lane >= o) s += t;
        }
        wsum[lane] = s;
    }
    __syncthreads();
    int excl = v - c + (w ? wsum[w - 1] : 0);
    if (gid < N_NODES) d_rowptr[gid] = excl;
    if (tid == 1023) d_bsum[blockIdx.x] = wsum[31];
}

__global__ void k_scan2() {
    __shared__ int s[128];
    const int t = threadIdx.x;
    s[t] = (t < SCAN_B) ? d_bsum[t] : 0;
    __syncthreads();
    for (int o = 1; o < 128; o <<= 1) {
        int v = (t >= o) ? s[t - o] : 0;
        __syncthreads();
        s[t] += v;
        __syncthreads();
    }
    if (t < SCAN_B) d_boff[t] = (t ? s[t - 1] : 0);
}

__global__ void k_scan3() {
    const int gid = blockIdx.x * blockDim.x + threadIdx.x;
    if (gid >= N_NODES) return;
    int rp = d_rowptr[gid] + d_boff[gid >> 10];
    d_rowptr[gid] = rp;
    d_cursor[gid] = rp;
    d_dinv[gid] = rsqrtf((float)(d_cnt[gid] + 1));  // +1 = self loop
}

__global__ void k_fill() {
    int e = blockIdx.x * blockDim.x + threadIdx.x;
    if (e >= NE) return;
    int dd = d_dst32[e];
    int pos = atomicAdd(&d_cursor[dd], 1);
    d_srcs[pos] = d_src32[e];
}

// ---------------- weight folding: W2h = W2 @ Wh, bh2 = b2 @ Wh + bh ---------
__global__ void k_fold(const float* __restrict__ W2,
                       const float* __restrict__ Wh,
                       const float* __restrict__ b2,
                       const float* __restrict__ bh) {
    const int i = threadIdx.x;           // 256 threads
    const int k = i >> 1, j = i & 1;
    float s = 0.f;
#pragma unroll 8
    for (int m = 0; m < HID; m++)
        s += W2[(size_t)k * HID + m] * Wh[m * 2 + j];
    d_w2h[k * 2 + j] = s;
    if (k == 0) {
        float t = bh[j];
        for (int m = 0; m < HID; m++) t += b2[m] * Wh[m * 2 + j];
        d_bh2[j] = t;
    }
}

// ---------------- tensor-core GEMM (round-10 config, verbatim) ---------------
// C[M,128] = act(A[M,K] @ W[K,128] + b), split-bf16 3-term compensation.
#define PAD 20
template <int K, bool RELU, bool BIAS>
__global__ void __launch_bounds__(256) k_gemm_tc(const float* __restrict__ A,
                                                 const float* __restrict__ W,
                                                 const float* __restrict__ bias,
                                                 float* __restrict__ C, int M) {
    __shared__ unsigned sAhi[128][PAD];
    __shared__ unsigned sAlo[128][PAD];
    __shared__ unsigned sWhi[128][PAD];
    __shared__ unsigned sWlo[128][PAD];

    const int tid   = threadIdx.x;
    const int warp  = tid >> 5;
    const int lane  = tid & 31;
    const int g     = lane >> 2;
    const int tig   = lane & 3;
    const int mbase = warp * 16;
    const int row0  = blockIdx.x * 128;

    float acc[16][4];
#pragma unroll
    for (int nb = 0; nb < 16; nb++)
#pragma unroll
        for (int i = 0; i < 4; i++) acc[nb][i] = 0.f;

    for (int kc = 0; kc < K; kc += 32) {
#pragma unroll
        for (int i = 0; i < 4; i++) {
            int idx = tid + i * 256;
            int r = idx >> 3, c4 = idx & 7;
            int grow = row0 + r;
            float4 v = make_float4(0.f, 0.f, 0.f, 0.f);
            if (grow < M)
                v = *(const float4*)(A + (size_t)grow * K + kc + c4 * 4);
            float hx = __bfloat162float(__float2bfloat16(v.x));
            float hy = __bfloat162float(__float2bfloat16(v.y));
            float hz = __bfloat162float(__float2bfloat16(v.z));
            float hw = __bfloat162float(__float2bfloat16(v.w));
            sAhi[r][c4 * 2 + 0] = pack_bf16x2(hx, hy);
            sAhi[r][c4 * 2 + 1] = pack_bf16x2(hz, hw);
            sAlo[r][c4 * 2 + 0] = pack_bf16x2(v.x - hx, v.y - hy);
            sAlo[r][c4 * 2 + 1] = pack_bf16x2(v.z - hz, v.w - hw);
        }
#pragma unroll
        for (int i = 0; i < 8; i++) {
            int idx = tid + i * 256;
            int n = idx & 127, kp = idx >> 7;
            float w0 = W[(size_t)(kc + 2 * kp)     * 128 + n];
            float w1 = W[(size_t)(kc + 2 * kp + 1) * 128 + n];
            float h0 = __bfloat162float(__float2bfloat16(w0));
            float h1 = __bfloat162float(__float2bfloat16(w1));
            sWhi[n][kp] = pack_bf16x2(h0, h1);
            sWlo[n][kp] = pack_bf16x2(w0 - h0, w1 - h1);
        }
        __syncthreads();

#pragma unroll
        for (int kk = 0; kk < 2; kk++) {
            const int kp = kk * 8 + tig;
            unsigned ah0 = sAhi[mbase + g][kp];
            unsigned ah1 = sAhi[mbase + g + 8][kp];
            unsigned ah2 = sAhi[mbase + g][kp + 4];
            unsigned ah3 = sAhi[mbase + g + 8][kp + 4];
            unsigned al0 = sAlo[mbase + g][kp];
            unsigned al1 = sAlo[mbase + g + 8][kp];
            unsigned al2 = sAlo[mbase + g][kp + 4];
            unsigned al3 = sAlo[mbase + g + 8][kp + 4];
#pragma unroll
            for (int nb = 0; nb < 16; nb++) {
                unsigned bh0 = sWhi[nb * 8 + g][kp];
                unsigned bh1 = sWhi[nb * 8 + g][kp + 4];
                unsigned bl0 = sWlo[nb * 8 + g][kp];
                unsigned bl1 = sWlo[nb * 8 + g][kp + 4];
                mma_bf16(acc[nb], ah0, ah1, ah2, ah3, bh0, bh1);  // hi*hi
                mma_bf16(acc[nb], ah0, ah1, ah2, ah3, bl0, bl1);  // hi*lo
                mma_bf16(acc[nb], al0, al1, al2, al3, bh0, bh1);  // lo*hi
            }
        }
        __syncthreads();
    }

    const int r0 = row0 + mbase + g;
    const int r1 = r0 + 8;
#pragma unroll
    for (int nb = 0; nb < 16; nb++) {
        int col = nb * 8 + tig * 2;
        float b0 = 0.f, b1 = 0.f;
        if (BIAS) { b0 = bias[col]; b1 = bias[col + 1]; }
        float2 v0, v1;
        v0.x = acc[nb][0] + b0; v0.y = acc[nb][1] + b1;
        v1.x = acc[nb][2] + b0; v1.y = acc[nb][3] + b1;
        if (RELU) {
            v0.x = fmaxf(v0.x, 0.f); v0.y = fmaxf(v0.y, 0.f);
            v1.x = fmaxf(v1.x, 0.f); v1.y = fmaxf(v1.y, 0.f);
        }
        if (r0 < M) *(float2*)(C + (size_t)r0 * 128 + col) = v0;
        if (r1 < M) *(float2*)(C + (size_t)r1 * 128 + col) = v1;
    }
}

// ---------------- GCN aggregate: 2 warps per node (64 features each) --------
// warp w -> node w>>1, feature half w&1; lane covers float2 (8B).
// 4-way neighbor unroll -> 4 independent gathers in flight.
__global__ void __launch_bounds__(256) k_aggregate(const float* __restrict__ t,
                                                   const float* __restrict__ b,
                                                   float* __restrict__ hout) {
    const int w    = (blockIdx.x * blockDim.x + threadIdx.x) >> 5;
    const int lane = threadIdx.x & 31;
    const int d    = w >> 1;
    const int half = w & 1;
    if (d >= N_NODES) return;

    const float2* t2 = (const float2*)t;          // row = 64 float2
    const int fo = half * 32 + lane;              // float2 index within row
    const float dd = d_dinv[d];

    float2 a0 = t2[(size_t)d * 64 + fo];          // self term
    a0.x *= dd; a0.y *= dd;
    float2 a1 = make_float2(0.f, 0.f);
    float2 a2 = make_float2(0.f, 0.f);
    float2 a3 = make_float2(0.f, 0.f);

    const int beg = d_rowptr[d];
    const int num = d_cnt[d];
    int j = 0;
    for (; j + 4 <= num; j += 4) {
        int s0 = d_srcs[beg + j];
        int s1 = d_srcs[beg + j + 1];
        int s2 = d_srcs[beg + j + 2];
        int s3 = d_srcs[beg + j + 3];
        float ds0 = d_dinv[s0], ds1 = d_dinv[s1];
        float ds2 = d_dinv[s2], ds3 = d_dinv[s3];
        float2 v0 = t2[(size_t)s0 * 64 + fo];
        float2 v1 = t2[(size_t)s1 * 64 + fo];
        float2 v2 = t2[(size_t)s2 * 64 + fo];
        float2 v3 = t2[(size_t)s3 * 64 + fo];
        a0.x += v0.x * ds0; a0.y += v0.y * ds0;
        a1.x += v1.x * ds1; a1.y += v1.y * ds1;
        a2.x += v2.x * ds2; a2.y += v2.y * ds2;
        a3.x += v3.x * ds3; a3.y += v3.y * ds3;
    }
    for (; j < num; j++) {
        int s = d_srcs[beg + j];
        float ds = d_dinv[s];
        float2 v = t2[(size_t)s * 64 + fo];
        a0.x += v.x * ds; a0.y += v.y * ds;
    }

    float2 bv = ((const float2*)b)[fo];
    float2 o;
    o.x = (a0.x + a1.x + a2.x + a3.x) * dd + bv.x;
    o.y = (a0.y + a1.y + a2.y + a3.y) * dd + bv.y;
    ((float2*)hout)[(size_t)d * 64 + fo] = o;
}

// ---------------- fused aggregate + head (4-way unroll) ---------------------
// out[d] = (P·h1)[d] @ W2h + bh2
__global__ void __launch_bounds__(256) k_agg_head(const float* __restrict__ h1,
                                                  float* __restrict__ out) {
    const int wid  = (blockIdx.x * blockDim.x + threadIdx.x) >> 5;
    const int lane = threadIdx.x & 31;
    if (wid >= N_NODES) return;
    const int d = wid;

    const float4* t4 = (const float4*)h1;
    const float dd = d_dinv[d];

    float4 a0 = t4[d * 32 + lane];   // self term
    a0.x *= dd; a0.y *= dd; a0.z *= dd; a0.w *= dd;
    float4 a1 = make_float4(0.f, 0.f, 0.f, 0.f);
    float4 a2 = make_float4(0.f, 0.f, 0.f, 0.f);
    float4 a3 = make_float4(0.f, 0.f, 0.f, 0.f);

    const int beg = d_rowptr[d];
    const int num = d_cnt[d];
    int j = 0;
    for (; j + 4 <= num; j += 4) {
        int s0 = d_srcs[beg + j];
        int s1 = d_srcs[beg + j + 1];
        int s2 = d_srcs[beg + j + 2];
        int s3 = d_srcs[beg + j + 3];
        float ds0 = d_dinv[s0], ds1 = d_dinv[s1];
        float ds2 = d_dinv[s2], ds3 = d_dinv[s3];
        float4 v0 = t4[s0 * 32 + lane];
        float4 v1 = t4[s1 * 32 + lane];
        float4 v2 = t4[s2 * 32 + lane];
        float4 v3 = t4[s3 * 32 + lane];
        a0.x += v0.x * ds0; a0.y += v0.y * ds0; a0.z += v0.z * ds0; a0.w += v0.w * ds0;
        a1.x += v1.x * ds1; a1.y += v1.y * ds1; a1.z += v1.z * ds1; a1.w += v1.w * ds1;
        a2.x += v2.x * ds2; a2.y += v2.y * ds2; a2.z += v2.z * ds2; a2.w += v2.w * ds2;
        a3.x += v3.x * ds3; a3.y += v3.y * ds3; a3.z += v3.z * ds3; a3.w += v3.w * ds3;
    }
    for (; j < num; j++) {
        int s = d_srcs[beg + j];
        float ds = d_dinv[s];
        float4 v = t4[s * 32 + lane];
        a0.x += v.x * ds; a0.y += v.y * ds; a0.z += v.z * ds; a0.w += v.w * ds;
    }

    float4 a;
    a.x = (a0.x + a1.x + a2.x + a3.x) * dd;
    a.y = (a0.y + a1.y + a2.y + a3.y) * dd;
    a.z = (a0.z + a1.z + a2.z + a3.z) * dd;
    a.w = (a0.w + a1.w + a2.w + a3.w) * dd;

    float4 w0 = *(const float4*)(d_w2h + lane * 8);
    float4 w1 = *(const float4*)(d_w2h + lane * 8 + 4);
    float p0 = a.x * w0.x + a.y * w0.z + a.z * w1.x + a.w * w1.z;
    float p1 = a.x * w0.y + a.y * w0.w + a.z * w1.y + a.w * w1.w;
#pragma unroll
    for (int off = 16; off; off >>= 1) {
        p0 += __shfl_xor_sync(0xFFFFFFFFu, p0, off);
        p1 += __shfl_xor_sync(0xFFFFFFFFu, p1, off);
    }
    if (lane == 0) {
        out[d * 2 + 0] = p0 + d_bh2[0];
        out[d * 2 + 1] = p1 + d_bh2[1];
    }
}

// ---------------- launch -----------------------------------------------------
extern "C" void kernel_launch(void* const* d_in, const int* in_sizes, int n_in,
                              void* d_out, int out_size) {
    const void*  ei = d_in[0];
    const float* x  = (const float*)d_in[1];
    const float* Wi = (const float*)d_in[2];
    const float* bi = (const float*)d_in[3];
    const float* W1 = (const float*)d_in[4];
    const float* b1 = (const float*)d_in[5];
    const float* W2 = (const float*)d_in[6];
    const float* b2 = (const float*)d_in[7];
    const float* Wh = (const float*)d_in[8];
    const float* bh = (const float*)d_in[9];
    float* out = (float*)d_out;

    float *h, *t;
    cudaGetSymbolAddress((void**)&h, d_h);
    cudaGetSymbolAddress((void**)&t, d_t);

    const int EB  = (NE + 255) / 256;
    const int NB  = (N_NODES + 255) / 256;
    const int GB  = (N_NODES + 127) / 128;
    const int WB  = (N_NODES + 7) / 8;
    const int WB2 = (2 * N_NODES + 7) / 8;   // feature-split aggregate

    // Launch order keeps the big GEMM at index 3 (ncu's capture slot).
    k_detect<<<1, 1>>>((const int*)ei);                                // 0
    k_zero_cnt<<<NB, 256>>>();                                         // 1
    k_convert_count<<<EB, 256>>>(ei);                                  // 2
    k_gemm_tc<IN_DIM, true, true><<<GB, 256>>>(x, Wi, bi, h, N_NODES); // 3 <- profiled
    k_scan1<<<SCAN_B, 1024>>>();                                       // 4
    k_scan2<<<1, 128>>>();                                             // 5
    k_scan3<<<NB, 256>>>();                                            // 6
    k_fill<<<EB, 256>>>();                                             // 7
    k_fold<<<1, 256>>>(W2, Wh, b2, bh);                                // 8

    // layer 1: t = h @ W1 ; h = P·t + b1
    k_gemm_tc<HID, false, false><<<GB, 256>>>(h, W1, nullptr, t, N_NODES);
    k_aggregate<<<WB2, 256>>>(t, b1, h);

    // layer 2 + head fused: out = (P·h) @ (W2@Wh) + (b2@Wh + bh)
    k_agg_head<<<WB, 256>>>(h, out);
}

// round 16
// speedup vs baseline: 1.1985x; 1.1960x over previous
#include <cuda_runtime.h>
#include <cuda_bf16.h>
#include <stdint.h>

#define N_NODES 100000
#define NE      1600000
#define IN_DIM  256
#define HID     128
#define SCAN_B  ((N_NODES + 1023) / 1024)   // 98 scan blocks

// ---------------- scratch (static device globals; no allocation) ------------
__device__ int   d_src32[NE];
__device__ int   d_dst32[NE];
__device__ int   d_srcs[NE];       // CSR-permuted source indices (by dst)
__device__ int   d_cnt[N_NODES];
__device__ int   d_rowptr[N_NODES];
__device__ int   d_cursor[N_NODES];
__device__ float d_dinv[N_NODES];
__device__ int   d_bsum[SCAN_B];
__device__ int   d_boff[SCAN_B];
__device__ float d_h[(size_t)N_NODES * HID];
__device__ float d_t[(size_t)N_NODES * HID];
__device__ float d_w2h[HID * 2];   // folded W2 @ Wh  [128,2]
__device__ float d_bh2[2];         // folded b2 @ Wh + bh
__device__ int   g_is64;

// ---------------- helpers -----------------------------------------------------
__device__ __forceinline__ unsigned pack_bf16x2(float k_even, float k_odd) {
    unsigned r;
    asm("cvt.rn.bf16x2.f32 %0, %1, %2;" : "=r"(r) : "f"(k_odd), "f"(k_even));
    return r;
}
__device__ __forceinline__ void mma_bf16(float* c, unsigned a0, unsigned a1,
                                         unsigned a2, unsigned a3,
                                         unsigned b0, unsigned b1) {
    asm("mma.sync.aligned.m16n8k16.row.col.f32.bf16.bf16.f32 "
        "{%0,%1,%2,%3}, {%4,%5,%6,%7}, {%8,%9}, {%0,%1,%2,%3};"
        : "+f"(c[0]), "+f"(c[1]), "+f"(c[2]), "+f"(c[3])
        : "r"(a0), "r"(a1), "r"(a2), "r"(a3), "r"(b0), "r"(b1));
}

// ---------------- edge dtype detection + conversion + count ------------------
__global__ void k_detect(const int* __restrict__ w) {
    int ok = 1;
    for (int i = 0; i < 64; i++) {
        if (w[2 * i + 1] != 0) { ok = 0; break; }
    }
    g_is64 = ok;
}

__global__ void k_zero_cnt() {
    int i = blockIdx.x * blockDim.x + threadIdx.x;
    if (i < N_NODES) d_cnt[i] = 0;
}

__global__ void k_convert_count(const void* __restrict__ ei) {
    int e = blockIdx.x * blockDim.x + threadIdx.x;
    if (e >= NE) return;
    int s, d;
    if (g_is64) {
        const long long* p = (const long long*)ei;
        s = (int)p[e];
        d = (int)p[e + NE];
    } else {
        const int* p = (const int*)ei;
        s = p[e];
        d = p[e + NE];
    }
    d_src32[e] = s;
    d_dst32[e] = d;
    atomicAdd(&d_cnt[d], 1);
}

// ---------------- parallel 3-phase scan --------------------------------------
__global__ void __launch_bounds__(1024) k_scan1() {
    __shared__ int wsum[32];
    const int tid  = threadIdx.x;
    const int lane = tid & 31;
    const int w    = tid >> 5;
    const int gid  = blockIdx.x * 1024 + tid;

    int c = (gid < N_NODES) ? d_cnt[gid] : 0;
    int v = c;
#pragma unroll
    for (int o = 1; o < 32; o <<= 1) {
        int t = __shfl_up_sync(0xFFFFFFFFu, v, o);
        if (lane >= o) v += t;
    }
    if (lane == 31) wsum[w] = v;
    __syncthreads();
    if (w == 0) {
        int s = wsum[lane];
#pragma unroll
        for (int o = 1; o < 32; o <<= 1) {
            int t = __shfl_up_sync(0xFFFFFFFFu, s, o);
            if (lane >= o) s += t;
        }
        wsum[lane] = s;
    }
    __syncthreads();
    int excl = v - c + (w ? wsum[w - 1] : 0);
    if (gid < N_NODES) d_rowptr[gid] = excl;
    if (tid == 1023) d_bsum[blockIdx.x] = wsum[31];
}

__global__ void k_scan2() {
    __shared__ int s[128];
    const int t = threadIdx.x;
    s[t] = (t < SCAN_B) ? d_bsum[t] : 0;
    __syncthreads();
    for (int o = 1; o < 128; o <<= 1) {
        int v = (t >= o) ? s[t - o] : 0;
        __syncthreads();
        s[t] += v;
        __syncthreads();
    }
    if (t < SCAN_B) d_boff[t] = (t ? s[t - 1] : 0);
}

__global__ void k_scan3() {
    const int gid = blockIdx.x * blockDim.x + threadIdx.x;
    if (gid >= N_NODES) return;
    int rp = d_rowptr[gid] + d_boff[gid >> 10];
    d_rowptr[gid] = rp;
    d_cursor[gid] = rp;
    d_dinv[gid] = rsqrtf((float)(d_cnt[gid] + 1));  // +1 = self loop
}

__global__ void k_fill() {
    int e = blockIdx.x * blockDim.x + threadIdx.x;
    if (e >= NE) return;
    int dd = d_dst32[e];
    int pos = atomicAdd(&d_cursor[dd], 1);
    d_srcs[pos] = d_src32[e];
}

// ---------------- weight folding: W2h = W2 @ Wh, bh2 = b2 @ Wh + bh ---------
__global__ void k_fold(const float* __restrict__ W2,
                       const float* __restrict__ Wh,
                       const float* __restrict__ b2,
                       const float* __restrict__ bh) {
    const int i = threadIdx.x;           // 256 threads
    const int k = i >> 1, j = i & 1;
    float s = 0.f;
#pragma unroll 8
    for (int m = 0; m < HID; m++)
        s += W2[(size_t)k * HID + m] * Wh[m * 2 + j];
    d_w2h[k * 2 + j] = s;
    if (k == 0) {
        float t = bh[j];
        for (int m = 0; m < HID; m++) t += b2[m] * Wh[m * 2 + j];
        d_bh2[j] = t;
    }
}

// ---------------- tensor-core GEMM (round-10 config + optional row scale) ----
// C[M,128] = act(A[M,K] @ W[K,128] + b), split-bf16 3-term compensation.
// SCALE: multiply output row r by d_dinv[r] (pre-normalize messages).
#define PAD 20
template <int K, bool RELU, bool BIAS, bool SCALE>
__global__ void __launch_bounds__(256) k_gemm_tc(const float* __restrict__ A,
                                                 const float* __restrict__ W,
                                                 const float* __restrict__ bias,
                                                 float* __restrict__ C, int M) {
    __shared__ unsigned sAhi[128][PAD];
    __shared__ unsigned sAlo[128][PAD];
    __shared__ unsigned sWhi[128][PAD];
    __shared__ unsigned sWlo[128][PAD];

    const int tid   = threadIdx.x;
    const int warp  = tid >> 5;
    const int lane  = tid & 31;
    const int g     = lane >> 2;
    const int tig   = lane & 3;
    const int mbase = warp * 16;
    const int row0  = blockIdx.x * 128;

    float acc[16][4];
#pragma unroll
    for (int nb = 0; nb < 16; nb++)
#pragma unroll
        for (int i = 0; i < 4; i++) acc[nb][i] = 0.f;

    for (int kc = 0; kc < K; kc += 32) {
#pragma unroll
        for (int i = 0; i < 4; i++) {
            int idx = tid + i * 256;
            int r = idx >> 3, c4 = idx & 7;
            int grow = row0 + r;
            float4 v = make_float4(0.f, 0.f, 0.f, 0.f);
            if (grow < M)
                v = *(const float4*)(A + (size_t)grow * K + kc + c4 * 4);
            float hx = __bfloat162float(__float2bfloat16(v.x));
            float hy = __bfloat162float(__float2bfloat16(v.y));
            float hz = __bfloat162float(__float2bfloat16(v.z));
            float hw = __bfloat162float(__float2bfloat16(v.w));
            sAhi[r][c4 * 2 + 0] = pack_bf16x2(hx, hy);
            sAhi[r][c4 * 2 + 1] = pack_bf16x2(hz, hw);
            sAlo[r][c4 * 2 + 0] = pack_bf16x2(v.x - hx, v.y - hy);
            sAlo[r][c4 * 2 + 1] = pack_bf16x2(v.z - hz, v.w - hw);
        }
#pragma unroll
        for (int i = 0; i < 8; i++) {
            int idx = tid + i * 256;
            int n = idx & 127, kp = idx >> 7;
            float w0 = W[(size_t)(kc + 2 * kp)     * 128 + n];
            float w1 = W[(size_t)(kc + 2 * kp + 1) * 128 + n];
            float h0 = __bfloat162float(__float2bfloat16(w0));
            float h1 = __bfloat162float(__float2bfloat16(w1));
            sWhi[n][kp] = pack_bf16x2(h0, h1);
            sWlo[n][kp] = pack_bf16x2(w0 - h0, w1 - h1);
        }
        __syncthreads();

#pragma unroll
        for (int kk = 0; kk < 2; kk++) {
            const int kp = kk * 8 + tig;
            unsigned ah0 = sAhi[mbase + g][kp];
            unsigned ah1 = sAhi[mbase + g + 8][kp];
            unsigned ah2 = sAhi[mbase + g][kp + 4];
            unsigned ah3 = sAhi[mbase + g + 8][kp + 4];
            unsigned al0 = sAlo[mbase + g][kp];
            unsigned al1 = sAlo[mbase + g + 8][kp];
            unsigned al2 = sAlo[mbase + g][kp + 4];
            unsigned al3 = sAlo[mbase + g + 8][kp + 4];
#pragma unroll
            for (int nb = 0; nb < 16; nb++) {
                unsigned bh0 = sWhi[nb * 8 + g][kp];
                unsigned bh1 = sWhi[nb * 8 + g][kp + 4];
                unsigned bl0 = sWlo[nb * 8 + g][kp];
                unsigned bl1 = sWlo[nb * 8 + g][kp + 4];
                mma_bf16(acc[nb], ah0, ah1, ah2, ah3, bh0, bh1);  // hi*hi
                mma_bf16(acc[nb], ah0, ah1, ah2, ah3, bl0, bl1);  // hi*lo
                mma_bf16(acc[nb], al0, al1, al2, al3, bh0, bh1);  // lo*hi
            }
        }
        __syncthreads();
    }

    const int r0 = row0 + mbase + g;
    const int r1 = r0 + 8;
    float sc0 = 1.f, sc1 = 1.f;
    if (SCALE) {
        if (r0 < M) sc0 = d_dinv[r0];
        if (r1 < M) sc1 = d_dinv[r1];
    }
#pragma unroll
    for (int nb = 0; nb < 16; nb++) {
        int col = nb * 8 + tig * 2;
        float b0 = 0.f, b1 = 0.f;
        if (BIAS) { b0 = bias[col]; b1 = bias[col + 1]; }
        float2 v0, v1;
        v0.x = acc[nb][0] + b0; v0.y = acc[nb][1] + b1;
        v1.x = acc[nb][2] + b0; v1.y = acc[nb][3] + b1;
        if (RELU) {
            v0.x = fmaxf(v0.x, 0.f); v0.y = fmaxf(v0.y, 0.f);
            v1.x = fmaxf(v1.x, 0.f); v1.y = fmaxf(v1.y, 0.f);
        }
        if (SCALE) {
            v0.x *= sc0; v0.y *= sc0;
            v1.x *= sc1; v1.y *= sc1;
        }
        if (r0 < M) *(float2*)(C + (size_t)r0 * 128 + col) = v0;
        if (r1 < M) *(float2*)(C + (size_t)r1 * 128 + col) = v1;
    }
}

// ---------------- GCN aggregate (layer 1), prescaled rows --------------------
// Input t' rows already scaled by dinv[src]. Output prescaled for layer 2:
// h1''[d] = dinv[d] * ( dd * S + b1 ) where S = t'[d] + sum_j t'[src_j].
__global__ void __launch_bounds__(256) k_aggregate(const float* __restrict__ t,
                                                   const float* __restrict__ b,
                                                   float* __restrict__ hout) {
    const int wid  = (blockIdx.x * blockDim.x + threadIdx.x) >> 5;
    const int lane = threadIdx.x & 31;
    if (wid >= N_NODES) return;
    const int d = wid;

    const float4* t4 = (const float4*)t;
    const float dd = d_dinv[d];

    float4 a0 = t4[d * 32 + lane];   // self term (already dinv[d]-scaled)
    float4 a1 = make_float4(0.f, 0.f, 0.f, 0.f);

    const int beg = d_rowptr[d];
    const int num = d_cnt[d];
    int j = 0;
    for (; j + 2 <= num; j += 2) {
        int s0 = d_srcs[beg + j];
        int s1 = d_srcs[beg + j + 1];
        float4 v0 = t4[s0 * 32 + lane];
        float4 v1 = t4[s1 * 32 + lane];
        a0.x += v0.x; a0.y += v0.y; a0.z += v0.z; a0.w += v0.w;
        a1.x += v1.x; a1.y += v1.y; a1.z += v1.z; a1.w += v1.w;
    }
    if (j < num) {
        int s = d_srcs[beg + j];
        float4 v = t4[s * 32 + lane];
        a0.x += v.x; a0.y += v.y; a0.z += v.z; a0.w += v.w;
    }

    float4 bv = ((const float4*)b)[lane];
    const float s2 = dd * dd;        // dinv[d] * dd
    float4 o;
    o.x = (a0.x + a1.x) * s2 + bv.x * dd;
    o.y = (a0.y + a1.y) * s2 + bv.y * dd;
    o.z = (a0.z + a1.z) * s2 + bv.z * dd;
    o.w = (a0.w + a1.w) * s2 + bv.w * dd;
    ((float4*)hout)[(size_t)d * 32 + lane] = o;
}

// ---------------- fused aggregate + head (prescaled rows) --------------------
// out[d] = ( dd * (h1''[d] + sum_j h1''[src_j]) ) @ W2h + bh2
__global__ void __launch_bounds__(256) k_agg_head(const float* __restrict__ h1,
                                                  float* __restrict__ out) {
    const int wid  = (blockIdx.x * blockDim.x + threadIdx.x) >> 5;
    const int lane = threadIdx.x & 31;
    if (wid >= N_NODES) return;
    const int d = wid;

    const float4* t4 = (const float4*)h1;
    const float dd = d_dinv[d];

    float4 a0 = t4[d * 32 + lane];   // self term (already dinv[d]-scaled)
    float4 a1 = make_float4(0.f, 0.f, 0.f, 0.f);

    const int beg = d_rowptr[d];
    const int num = d_cnt[d];
    int j = 0;
    for (; j + 2 <= num; j += 2) {
        int s0 = d_srcs[beg + j];
        int s1 = d_srcs[beg + j + 1];
        float4 v0 = t4[s0 * 32 + lane];
        float4 v1 = t4[s1 * 32 + lane];
        a0.x += v0.x; a0.y += v0.y; a0.z += v0.z; a0.w += v0.w;
        a1.x += v1.x; a1.y += v1.y; a1.z += v1.z; a1.w += v1.w;
    }
    if (j < num) {
        int s = d_srcs[beg + j];
        float4 v = t4[s * 32 + lane];
        a0.x += v.x; a0.y += v.y; a0.z += v.z; a0.w += v.w;
    }

    float4 a;
    a.x = (a0.x + a1.x) * dd;
    a.y = (a0.y + a1.y) * dd;
    a.z = (a0.z + a1.z) * dd;
    a.w = (a0.w + a1.w) * dd;

    float4 w0 = *(const float4*)(d_w2h + lane * 8);
    float4 w1 = *(const float4*)(d_w2h + lane * 8 + 4);
    float p0 = a.x * w0.x + a.y * w0.z + a.z * w1.x + a.w * w1.z;
    float p1 = a.x * w0.y + a.y * w0.w + a.z * w1.y + a.w * w1.w;
#pragma unroll
    for (int off = 16; off; off >>= 1) {
        p0 += __shfl_xor_sync(0xFFFFFFFFu, p0, off);
        p1 += __shfl_xor_sync(0xFFFFFFFFu, p1, off);
    }
    if (lane == 0) {
        out[d * 2 + 0] = p0 + d_bh2[0];
        out[d * 2 + 1] = p1 + d_bh2[1];
    }
}

// ---------------- launch -----------------------------------------------------
extern "C" void kernel_launch(void* const* d_in, const int* in_sizes, int n_in,
                              void* d_out, int out_size) {
    const void*  ei = d_in[0];
    const float* x  = (const float*)d_in[1];
    const float* Wi = (const float*)d_in[2];
    const float* bi = (const float*)d_in[3];
    const float* W1 = (const float*)d_in[4];
    const float* b1 = (const float*)d_in[5];
    const float* W2 = (const float*)d_in[6];
    const float* b2 = (const float*)d_in[7];
    const float* Wh = (const float*)d_in[8];
    const float* bh = (const float*)d_in[9];
    float* out = (float*)d_out;

    float *h, *t;
    cudaGetSymbolAddress((void**)&h, d_h);
    cudaGetSymbolAddress((void**)&t, d_t);

    const int EB = (NE + 255) / 256;
    const int NB = (N_NODES + 255) / 256;
    const int GB = (N_NODES + 127) / 128;
    const int WB = (N_NODES + 7) / 8;

    // Launch order keeps the big GEMM at index 3 (ncu's capture slot).
    k_detect<<<1, 1>>>((const int*)ei);                                       // 0
    k_zero_cnt<<<NB, 256>>>();                                                // 1
    k_convert_count<<<EB, 256>>>(ei);                                         // 2
    k_gemm_tc<IN_DIM, true, true, false><<<GB, 256>>>(x, Wi, bi, h, N_NODES); // 3 <- profiled
    k_scan1<<<SCAN_B, 1024>>>();                                              // 4
    k_scan2<<<1, 128>>>();                                                    // 5
    k_scan3<<<NB, 256>>>();                                                   // 6
    k_fill<<<EB, 256>>>();                                                    // 7
    k_fold<<<1, 256>>>(W2, Wh, b2, bh);                                       // 8

    // layer 1: t' = dinv ⊙ (h @ W1) ; h1'' = dinv ⊙ (P·t' + b1)
    k_gemm_tc<HID, false, false, true><<<GB, 256>>>(h, W1, nullptr, t, N_NODES);
    k_aggregate<<<WB, 256>>>(t, b1, h);

    // layer 2 + head fused: out = (P·h1) @ (W2@Wh) + (b2@Wh + bh)
    k_agg_head<<<WB, 256>>>(h, out);
}

// round 17
// speedup vs baseline: 1.3030x; 1.0872x over previous
#include <cuda_runtime.h>
#include <cuda_bf16.h>
#include <stdint.h>

#define N_NODES 100000
#define NE      1600000
#define IN_DIM  256
#define HID     128
#define SCAN_B  ((N_NODES + 1023) / 1024)   // 98 scan blocks

// ---------------- scratch (static device globals; no allocation) ------------
__device__ int   d_src32[NE];
__device__ int   d_dst32[NE];
__device__ int   d_srcs[NE];       // CSR-permuted source indices (by dst)
__device__ int   d_cnt[N_NODES];
__device__ int   d_rowptr[N_NODES];
__device__ int   d_cursor[N_NODES];
__device__ float d_dinv[N_NODES];
__device__ int   d_bsum[SCAN_B];
__device__ int   d_boff[SCAN_B];
__device__ float d_h[(size_t)N_NODES * HID];
__device__ float d_t[(size_t)N_NODES * HID];
__device__ float d_w2h[HID * 2];   // folded W2 @ Wh  [128,2]
__device__ float d_bh2[2];         // folded b2 @ Wh + bh
__device__ int   g_is64;

// ---------------- helpers -----------------------------------------------------
__device__ __forceinline__ unsigned pack_bf16x2(float k_even, float k_odd) {
    unsigned r;
    asm("cvt.rn.bf16x2.f32 %0, %1, %2;" : "=r"(r) : "f"(k_odd), "f"(k_even));
    return r;
}
__device__ __forceinline__ void mma_bf16(float* c, unsigned a0, unsigned a1,
                                         unsigned a2, unsigned a3,
                                         unsigned b0, unsigned b1) {
    asm("mma.sync.aligned.m16n8k16.row.col.f32.bf16.bf16.f32 "
        "{%0,%1,%2,%3}, {%4,%5,%6,%7}, {%8,%9}, {%0,%1,%2,%3};"
        : "+f"(c[0]), "+f"(c[1]), "+f"(c[2]), "+f"(c[3])
        : "r"(a0), "r"(a1), "r"(a2), "r"(a3), "r"(b0), "r"(b1));
}
__device__ __forceinline__ void cp_async16(void* dst, const void* src, bool pred) {
    unsigned u = (unsigned)__cvta_generic_to_shared(dst);
    int sz = pred ? 16 : 0;          // src-size 0 -> zero-fill 16B
    asm volatile("cp.async.cg.shared.global [%0], [%1], 16, %2;"
                 :: "r"(u), "l"(src), "r"(sz));
}
#define CP_COMMIT() asm volatile("cp.async.commit_group;" ::: "memory")
#define CP_WAIT0()  asm volatile("cp.async.wait_group 0;" ::: "memory")

// ---------------- edge dtype detection + conversion + count ------------------
__global__ void k_detect(const int* __restrict__ w) {
    int ok = 1;
    for (int i = 0; i < 64; i++) {
        if (w[2 * i + 1] != 0) { ok = 0; break; }
    }
    g_is64 = ok;
}

__global__ void k_zero_cnt() {
    int i = blockIdx.x * blockDim.x + threadIdx.x;
    if (i < N_NODES) d_cnt[i] = 0;
}

__global__ void k_convert_count(const void* __restrict__ ei) {
    int e = blockIdx.x * blockDim.x + threadIdx.x;
    if (e >= NE) return;
    int s, d;
    if (g_is64) {
        const long long* p = (const long long*)ei;
        s = (int)p[e];
        d = (int)p[e + NE];
    } else {
        const int* p = (const int*)ei;
        s = p[e];
        d = p[e + NE];
    }
    d_src32[e] = s;
    d_dst32[e] = d;
    atomicAdd(&d_cnt[d], 1);
}

// ---------------- parallel 3-phase scan --------------------------------------
__global__ void __launch_bounds__(1024) k_scan1() {
    __shared__ int wsum[32];
    const int tid  = threadIdx.x;
    const int lane = tid & 31;
    const int w    = tid >> 5;
    const int gid  = blockIdx.x * 1024 + tid;

    int c = (gid < N_NODES) ? d_cnt[gid] : 0;
    int v = c;
#pragma unroll
    for (int o = 1; o < 32; o <<= 1) {
        int t = __shfl_up_sync(0xFFFFFFFFu, v, o);
        if (lane >= o) v += t;
    }
    if (lane == 31) wsum[w] = v;
    __syncthreads();
    if (w == 0) {
        int s = wsum[lane];
#pragma unroll
        for (int o = 1; o < 32; o <<= 1) {
            int t = __shfl_up_sync(0xFFFFFFFFu, s, o);
            if (lane >= o) s += t;
        }
        wsum[lane] = s;
    }
    __syncthreads();
    int excl = v - c + (w ? wsum[w - 1] : 0);
    if (gid < N_NODES) d_rowptr[gid] = excl;
    if (tid == 1023) d_bsum[blockIdx.x] = wsum[31];
}

__global__ void k_scan2() {
    __shared__ int s[128];
    const int t = threadIdx.x;
    s[t] = (t < SCAN_B) ? d_bsum[t] : 0;
    __syncthreads();
    for (int o = 1; o < 128; o <<= 1) {
        int v = (t >= o) ? s[t - o] : 0;
        __syncthreads();
        s[t] += v;
        __syncthreads();
    }
    if (t < SCAN_B) d_boff[t] = (t ? s[t - 1] : 0);
}

__global__ void k_scan3() {
    const int gid = blockIdx.x * blockDim.x + threadIdx.x;
    if (gid >= N_NODES) return;
    int rp = d_rowptr[gid] + d_boff[gid >> 10];
    d_rowptr[gid] = rp;
    d_cursor[gid] = rp;
    d_dinv[gid] = rsqrtf((float)(d_cnt[gid] + 1));  // +1 = self loop
}

__global__ void k_fill() {
    int e = blockIdx.x * blockDim.x + threadIdx.x;
    if (e >= NE) return;
    int dd = d_dst32[e];
    int pos = atomicAdd(&d_cursor[dd], 1);
    d_srcs[pos] = d_src32[e];
}

// ---------------- weight folding: W2h = W2 @ Wh, bh2 = b2 @ Wh + bh ---------
__global__ void k_fold(const float* __restrict__ W2,
                       const float* __restrict__ Wh,
                       const float* __restrict__ b2,
                       const float* __restrict__ bh) {
    const int i = threadIdx.x;           // 256 threads
    const int k = i >> 1, j = i & 1;
    float s = 0.f;
#pragma unroll 8
    for (int m = 0; m < HID; m++)
        s += W2[(size_t)k * HID + m] * Wh[m * 2 + j];
    d_w2h[k * 2 + j] = s;
    if (k == 0) {
        float t = bh[j];
        for (int m = 0; m < HID; m++) t += b2[m] * Wh[m * 2 + j];
        d_bh2[j] = t;
    }
}

// ---------------- tensor-core GEMM with cp.async staging ---------------------
// C[M,128] = act(A[M,K] @ W[K,128] + b), split-bf16 3-term compensation.
// Chunk ch+1 raw tiles stream global->smem via cp.async while chunk ch's MMAs
// run; convert is smem->smem. SCALE: multiply output row r by d_dinv[r].
#define PAD 20
#define SM_RAWA 0                    // 1024 float4 = 16 KB
#define SM_RAWW 16384                // 1024 float4 = 16 KB
#define SM_AHI  32768                // each split buf 128*PAD*4 = 10240 B
#define SM_ALO  (SM_AHI + 10240)
#define SM_WHI  (SM_ALO + 10240)
#define SM_WLO  (SM_WHI + 10240)
#define SM_TOT  (SM_WLO + 10240)     // 73728 B

template <int K, bool RELU, bool BIAS, bool SCALE>
__global__ void __launch_bounds__(256) k_gemm_tc(const float* __restrict__ A,
                                                 const float* __restrict__ W,
                                                 const float* __restrict__ bias,
                                                 float* __restrict__ C, int M) {
    extern __shared__ char smem[];
    float4* rawA = (float4*)(smem + SM_RAWA);
    float4* rawW = (float4*)(smem + SM_RAWW);
    unsigned (*sAhi)[PAD] = (unsigned(*)[PAD])(smem + SM_AHI);
    unsigned (*sAlo)[PAD] = (unsigned(*)[PAD])(smem + SM_ALO);
    unsigned (*sWhi)[PAD] = (unsigned(*)[PAD])(smem + SM_WHI);
    unsigned (*sWlo)[PAD] = (unsigned(*)[PAD])(smem + SM_WLO);

    const int tid   = threadIdx.x;
    const int warp  = tid >> 5;
    const int lane  = tid & 31;
    const int g     = lane >> 2;
    const int tig   = lane & 3;
    const int mbase = warp * 16;
    const int row0  = blockIdx.x * 128;
    constexpr int NCHUNK = K / 32;

    float acc[16][4];
#pragma unroll
    for (int nb = 0; nb < 16; nb++)
#pragma unroll
        for (int i = 0; i < 4; i++) acc[nb][i] = 0.f;

    // ---- prefetch chunk 0 ---------------------------------------------------
    {
        const int kc = 0;
#pragma unroll
        for (int i = 0; i < 4; i++) {
            int idx = tid + i * 256;
            int r = idx >> 3, c4 = idx & 7;
            int grow = row0 + r;
            bool ok = grow < M;
            const float* src = A + (size_t)(ok ? grow : 0) * K + kc + c4 * 4;
            cp_async16(&rawA[idx], src, ok);
        }
#pragma unroll
        for (int i = 0; i < 4; i++) {
            int idx = tid + i * 256;
            int kr = idx >> 5, c4 = idx & 31;
            cp_async16(&rawW[idx], W + (size_t)(kc + kr) * 128 + c4 * 4, true);
        }
        CP_COMMIT();
    }

    for (int ch = 0; ch < NCHUNK; ch++) {
        CP_WAIT0();
        __syncthreads();           // raw(ch) visible; prior MMA reads done

        // ---- convert raw -> split (smem to smem) ----------------------------
#pragma unroll
        for (int i = 0; i < 4; i++) {
            int idx = tid + i * 256;
            int r = idx >> 3, c4 = idx & 7;
            float4 v = rawA[idx];
            float hx = __bfloat162float(__float2bfloat16(v.x));
            float hy = __bfloat162float(__float2bfloat16(v.y));
            float hz = __bfloat162float(__float2bfloat16(v.z));
            float hw = __bfloat162float(__float2bfloat16(v.w));
            sAhi[r][c4 * 2 + 0] = pack_bf16x2(hx, hy);
            sAhi[r][c4 * 2 + 1] = pack_bf16x2(hz, hw);
            sAlo[r][c4 * 2 + 0] = pack_bf16x2(v.x - hx, v.y - hy);
            sAlo[r][c4 * 2 + 1] = pack_bf16x2(v.z - hz, v.w - hw);
        }
        const float* rawWf = (const float*)rawW;
#pragma unroll
        for (int i = 0; i < 8; i++) {
            int idx = tid + i * 256;
            int n = idx & 127, kp = idx >> 7;
            float w0 = rawWf[(2 * kp)     * 128 + n];
            float w1 = rawWf[(2 * kp + 1) * 128 + n];
            float h0 = __bfloat162float(__float2bfloat16(w0));
            float h1 = __bfloat162float(__float2bfloat16(w1));
            sWhi[n][kp] = pack_bf16x2(h0, h1);
            sWlo[n][kp] = pack_bf16x2(w0 - h0, w1 - h1);
        }
        __syncthreads();           // split ready; raw free for reuse

        // ---- issue prefetch of chunk ch+1 (overlaps with MMAs below) --------
        if (ch + 1 < NCHUNK) {
            const int kc = (ch + 1) * 32;
#pragma unroll
            for (int i = 0; i < 4; i++) {
                int idx = tid + i * 256;
                int r = idx >> 3, c4 = idx & 7;
                int grow = row0 + r;
                bool ok = grow < M;
                const float* src = A + (size_t)(ok ? grow : 0) * K + kc + c4 * 4;
                cp_async16(&rawA[idx], src, ok);
            }
#pragma unroll
            for (int i = 0; i < 4; i++) {
                int idx = tid + i * 256;
                int kr = idx >> 5, c4 = idx & 31;
                cp_async16(&rawW[idx], W + (size_t)(kc + kr) * 128 + c4 * 4, true);
            }
            CP_COMMIT();
        }

        // ---- MMAs -----------------------------------------------------------
#pragma unroll
        for (int kk = 0; kk < 2; kk++) {
            const int kp = kk * 8 + tig;
            unsigned ah0 = sAhi[mbase + g][kp];
            unsigned ah1 = sAhi[mbase + g + 8][kp];
            unsigned ah2 = sAhi[mbase + g][kp + 4];
            unsigned ah3 = sAhi[mbase + g + 8][kp + 4];
            unsigned al0 = sAlo[mbase + g][kp];
            unsigned al1 = sAlo[mbase + g + 8][kp];
            unsigned al2 = sAlo[mbase + g][kp + 4];
            unsigned al3 = sAlo[mbase + g + 8][kp + 4];
#pragma unroll
            for (int nb = 0; nb < 16; nb++) {
                unsigned bh0 = sWhi[nb * 8 + g][kp];
                unsigned bh1 = sWhi[nb * 8 + g][kp + 4];
                unsigned bl0 = sWlo[nb * 8 + g][kp];
                unsigned bl1 = sWlo[nb * 8 + g][kp + 4];
                mma_bf16(acc[nb], ah0, ah1, ah2, ah3, bh0, bh1);  // hi*hi
                mma_bf16(acc[nb], ah0, ah1, ah2, ah3, bl0, bl1);  // hi*lo
                mma_bf16(acc[nb], al0, al1, al2, al3, bh0, bh1);  // lo*hi
            }
        }
    }

    // ---- epilogue -----------------------------------------------------------
    const int r0 = row0 + mbase + g;
    const int r1 = r0 + 8;
    float sc0 = 1.f, sc1 = 1.f;
    if (SCALE) {
        if (r0 < M) sc0 = d_dinv[r0];
        if (r1 < M) sc1 = d_dinv[r1];
    }
#pragma unroll
    for (int nb = 0; nb < 16; nb++) {
        int col = nb * 8 + tig * 2;
        float b0 = 0.f, b1 = 0.f;
        if (BIAS) { b0 = bias[col]; b1 = bias[col + 1]; }
        float2 v0, v1;
        v0.x = acc[nb][0] + b0; v0.y = acc[nb][1] + b1;
        v1.x = acc[nb][2] + b0; v1.y = acc[nb][3] + b1;
        if (RELU) {
            v0.x = fmaxf(v0.x, 0.f); v0.y = fmaxf(v0.y, 0.f);
            v1.x = fmaxf(v1.x, 0.f); v1.y = fmaxf(v1.y, 0.f);
        }
        if (SCALE) {
            v0.x *= sc0; v0.y *= sc0;
            v1.x *= sc1; v1.y *= sc1;
        }
        if (r0 < M) *(float2*)(C + (size_t)r0 * 128 + col) = v0;
        if (r1 < M) *(float2*)(C + (size_t)r1 * 128 + col) = v1;
    }
}

// ---------------- GCN aggregate (layer 1), prescaled rows --------------------
__global__ void __launch_bounds__(256) k_aggregate(const float* __restrict__ t,
                                                   const float* __restrict__ b,
                                                   float* __restrict__ hout) {
    const int wid  = (blockIdx.x * blockDim.x + threadIdx.x) >> 5;
    const int lane = threadIdx.x & 31;
    if (wid >= N_NODES) return;
    const int d = wid;

    const float4* t4 = (const float4*)t;
    const float dd = d_dinv[d];

    float4 a0 = t4[d * 32 + lane];   // self term (already dinv[d]-scaled)
    float4 a1 = make_float4(0.f, 0.f, 0.f, 0.f);

    const int beg = d_rowptr[d];
    const int num = d_cnt[d];
    int j = 0;
    for (; j + 2 <= num; j += 2) {
        int s0 = d_srcs[beg + j];
        int s1 = d_srcs[beg + j + 1];
        float4 v0 = t4[s0 * 32 + lane];
        float4 v1 = t4[s1 * 32 + lane];
        a0.x += v0.x; a0.y += v0.y; a0.z += v0.z; a0.w += v0.w;
        a1.x += v1.x; a1.y += v1.y; a1.z += v1.z; a1.w += v1.w;
    }
    if (j < num) {
        int s = d_srcs[beg + j];
        float4 v = t4[s * 32 + lane];
        a0.x += v.x; a0.y += v.y; a0.z += v.z; a0.w += v.w;
    }

    float4 bv = ((const float4*)b)[lane];
    const float s2 = dd * dd;
    float4 o;
    o.x = (a0.x + a1.x) * s2 + bv.x * dd;
    o.y = (a0.y + a1.y) * s2 + bv.y * dd;
    o.z = (a0.z + a1.z) * s2 + bv.z * dd;
    o.w = (a0.w + a1.w) * s2 + bv.w * dd;
    ((float4*)hout)[(size_t)d * 32 + lane] = o;
}

// ---------------- fused aggregate + head (prescaled rows) --------------------
__global__ void __launch_bounds__(256) k_agg_head(const float* __restrict__ h1,
                                                  float* __restrict__ out) {
    const int wid  = (blockIdx.x * blockDim.x + threadIdx.x) >> 5;
    const int lane = threadIdx.x & 31;
    if (wid >= N_NODES) return;
    const int d = wid;

    const float4* t4 = (const float4*)h1;
    const float dd = d_dinv[d];

    float4 a0 = t4[d * 32 + lane];   // self term (already dinv[d]-scaled)
    float4 a1 = make_float4(0.f, 0.f, 0.f, 0.f);

    const int beg = d_rowptr[d];
    const int num = d_cnt[d];
    int j = 0;
    for (; j + 2 <= num; j += 2) {
        int s0 = d_srcs[beg + j];
        int s1 = d_srcs[beg + j + 1];
        float4 v0 = t4[s0 * 32 + lane];
        float4 v1 = t4[s1 * 32 + lane];
        a0.x += v0.x; a0.y += v0.y; a0.z += v0.z; a0.w += v0.w;
        a1.x += v1.x; a1.y += v1.y; a1.z += v1.z; a1.w += v1.w;
    }
    if (j < num) {
        int s = d_srcs[beg + j];
        float4 v = t4[s * 32 + lane];
        a0.x += v.x; a0.y += v.y; a0.z += v.z; a0.w += v.w;
    }

    float4 a;
    a.x = (a0.x + a1.x) * dd;
    a.y = (a0.y + a1.y) * dd;
    a.z = (a0.z + a1.z) * dd;
    a.w = (a0.w + a1.w) * dd;

    float4 w0 = *(const float4*)(d_w2h + lane * 8);
    float4 w1 = *(const float4*)(d_w2h + lane * 8 + 4);
    float p0 = a.x * w0.x + a.y * w0.z + a.z * w1.x + a.w * w1.z;
    float p1 = a.x * w0.y + a.y * w0.w + a.z * w1.y + a.w * w1.w;
#pragma unroll
    for (int off = 16; off; off >>= 1) {
        p0 += __shfl_xor_sync(0xFFFFFFFFu, p0, off);
        p1 += __shfl_xor_sync(0xFFFFFFFFu, p1, off);
    }
    if (lane == 0) {
        out[d * 2 + 0] = p0 + d_bh2[0];
        out[d * 2 + 1] = p1 + d_bh2[1];
    }
}

// ---------------- launch -----------------------------------------------------
extern "C" void kernel_launch(void* const* d_in, const int* in_sizes, int n_in,
                              void* d_out, int out_size) {
    const void*  ei = d_in[0];
    const float* x  = (const float*)d_in[1];
    const float* Wi = (const float*)d_in[2];
    const float* bi = (const float*)d_in[3];
    const float* W1 = (const float*)d_in[4];
    const float* b1 = (const float*)d_in[5];
    const float* W2 = (const float*)d_in[6];
    const float* b2 = (const float*)d_in[7];
    const float* Wh = (const float*)d_in[8];
    const float* bh = (const float*)d_in[9];
    float* out = (float*)d_out;

    float *h, *t;
    cudaGetSymbolAddress((void**)&h, d_h);
    cudaGetSymbolAddress((void**)&t, d_t);

    // Dynamic smem opt-in (host API; not a stream op, safe under capture)
    static int attr_done = 0;
    if (!attr_done) {
        cudaFuncSetAttribute(k_gemm_tc<IN_DIM, true, true, false>,
                             cudaFuncAttributeMaxDynamicSharedMemorySize, SM_TOT);
        cudaFuncSetAttribute(k_gemm_tc<HID, false, false, true>,
                             cudaFuncAttributeMaxDynamicSharedMemorySize, SM_TOT);
        attr_done = 1;
    }

    const int EB = (NE + 255) / 256;
    const int NB = (N_NODES + 255) / 256;
    const int GB = (N_NODES + 127) / 128;
    const int WB = (N_NODES + 7) / 8;

    // Launch order keeps the big GEMM at index 3 (ncu's capture slot).
    k_detect<<<1, 1>>>((const int*)ei);                                       // 0
    k_zero_cnt<<<NB, 256>>>();                                                // 1
    k_convert_count<<<EB, 256>>>(ei);                                         // 2
    k_gemm_tc<IN_DIM, true, true, false><<<GB, 256, SM_TOT>>>(x, Wi, bi, h, N_NODES); // 3 <- profiled
    k_scan1<<<SCAN_B, 1024>>>();                                              // 4
    k_scan2<<<1, 128>>>();                                                    // 5
    k_scan3<<<NB, 256>>>();                                                   // 6
    k_fill<<<EB, 256>>>();                                                    // 7
    k_fold<<<1, 256>>>(W2, Wh, b2, bh);                                       // 8

    // layer 1: t' = dinv ⊙ (h @ W1) ; h1'' = dinv ⊙ (P·t' + b1)
    k_gemm_tc<HID, false, false, true><<<GB, 256, SM_TOT>>>(h, W1, nullptr, t, N_NODES);
    k_aggregate<<<WB, 256>>>(t, b1, h);

    // layer 2 + head fused: out = (P·h1) @ (W2@Wh) + (b2@Wh + bh)
    k_agg_head<<<WB, 256>>>(h, out);
}